// round 4
// baseline (speedup 1.0000x reference)
#include <cuda_runtime.h>
#include <cstddef>

#define BN 4
#define NN 1024
#define CC 64
#define ROWS (BN*NN)   // 4096
#define IB 4           // i-rows per logits block
#define JC 128         // j chunk per smem tile

// scratch for projections (device globals: no allocation allowed)
__device__ float g_x1[ROWS*CC];
__device__ float g_x2[ROWS*CC];

__device__ __forceinline__ float tanh_fast(float x){
    float y; asm("tanh.approx.f32 %0, %1;" : "=f"(y) : "f"(x)); return y;
}
__device__ __forceinline__ float ex2_fast(float x){
    float y; asm("ex2.approx.f32 %0, %1;" : "=f"(y) : "f"(x)); return y;
}
#define LOG2E 1.4426950408889634f

// ---------------------------------------------------------------------------
// Kernel 1: x1 = x @ W1^T, x2 = x @ W2^T   (x:[4096,64], W:[64,64] row-major)
// block = 256 threads, handles 2 rows; thread (m,rr,d) computes one output.
// ---------------------------------------------------------------------------
__global__ __launch_bounds__(256) void proj_kernel(const float* __restrict__ x,
                                                   const float* __restrict__ W1,
                                                   const float* __restrict__ W2){
    __shared__ float Ws[2][64][65];   // pad 65 -> bank = (d + c) % 32, conflict-free
    __shared__ float xs[2][64];
    int t = threadIdx.x;

    const float4* w1v = (const float4*)W1;
    const float4* w2v = (const float4*)W2;
    #pragma unroll
    for (int p = 0; p < 4; p++){
        int idx = p*256 + t;            // float4 index 0..1023
        int d = idx >> 4, c4 = (idx & 15) * 4;
        float4 v = w1v[idx];
        Ws[0][d][c4+0]=v.x; Ws[0][d][c4+1]=v.y; Ws[0][d][c4+2]=v.z; Ws[0][d][c4+3]=v.w;
        v = w2v[idx];
        Ws[1][d][c4+0]=v.x; Ws[1][d][c4+1]=v.y; Ws[1][d][c4+2]=v.z; Ws[1][d][c4+3]=v.w;
    }
    int row0 = blockIdx.x * 2;
    if (t < 32){
        int rr = t >> 4, c4 = (t & 15) * 4;
        float4 v = ((const float4*)(x + (size_t)(row0+rr)*CC))[t & 15];
        xs[rr][c4+0]=v.x; xs[rr][c4+1]=v.y; xs[rr][c4+2]=v.z; xs[rr][c4+3]=v.w;
    }
    __syncthreads();

    int m  = t >> 7;          // 0 -> x1, 1 -> x2
    int rr = (t >> 6) & 1;
    int d  = t & 63;
    float acc = 0.f;
    #pragma unroll
    for (int c = 0; c < 64; c++)
        acc = fmaf(xs[rr][c], Ws[m][d][c], acc);
    float* dst = m ? g_x2 : g_x1;
    dst[(size_t)(row0+rr)*CC + d] = acc;
}

// ---------------------------------------------------------------------------
// Kernel 2: logits[b,i,j] = sum_c w3[c]*tanh(x1[b,i,c]+x2[b,j,c])  -> d_out
// block = 256 threads (8 warps). IB=4 i-rows per block; warp pair per i.
// x2 staged in transposed smem tile [c][j] so inner reads are conflict-free.
// MUFU(tanh)-bound by design.
// ---------------------------------------------------------------------------
__global__ __launch_bounds__(256) void logits_kernel(const float* __restrict__ w3f,
                                                     float* __restrict__ out){
    __shared__ float x2s[CC][JC+1];
    __shared__ float z1s[IB][CC];
    __shared__ float w3s[CC];

    int t = threadIdx.x;
    int lane = t & 31, w = t >> 5;
    int blk = blockIdx.x;                 // 0..1023
    int b  = blk >> 8;                    // 256 blocks per batch
    int i0 = (blk & 255) * IB;

    if (t < IB*CC/4){                     // 64 float4: z1 rows
        float4 v = ((const float4*)(g_x1 + ((size_t)b*NN + i0)*CC))[t];
        int ii = t >> 4, c4 = (t & 15) * 4;
        z1s[ii][c4+0]=v.x; z1s[ii][c4+1]=v.y; z1s[ii][c4+2]=v.z; z1s[ii][c4+3]=v.w;
    } else if (t >= 64 && t < 80){        // 16 float4: w3
        float4 v = ((const float4*)w3f)[t-64];
        int c4 = (t-64)*4;
        w3s[c4+0]=v.x; w3s[c4+1]=v.y; w3s[c4+2]=v.z; w3s[c4+3]=v.w;
    }

    const float* x2base = g_x2 + (size_t)b*NN*CC;
    int il = w >> 1, half = w & 1;        // 2 warps per i-row
    int i = i0 + il;
    float* orowbase = out + ((size_t)b*NN + i)*NN;

    for (int jc = 0; jc < NN/JC; jc++){
        __syncthreads();
        // stage x2[jc*JC .. +JC) transposed: x2s[c][j]
        #pragma unroll
        for (int p = 0; p < (JC*CC/4)/256; p++){   // 8 float4 per thread
            int idx = p*256 + t;
            int j = idx >> 4, c4 = (idx & 15) * 4;
            float4 v = ((const float4*)(x2base + (size_t)(jc*JC + j)*CC))[idx & 15];
            x2s[c4+0][j]=v.x; x2s[c4+1][j]=v.y; x2s[c4+2][j]=v.z; x2s[c4+3][j]=v.w;
        }
        __syncthreads();

        float* orow = orowbase + jc*JC;
        #pragma unroll 1
        for (int gg = 0; gg < 2; gg++){
            int jj = (half*2 + gg)*32 + lane;
            float acc = 0.f;
            #pragma unroll
            for (int c = 0; c < CC; c++)
                acc = fmaf(w3s[c], tanh_fast(z1s[il][c] + x2s[c][jj]), acc);
            orow[jj] = acc;
        }
    }
}

// ---------------------------------------------------------------------------
// Kernel 3: in-place row softmax over last dim (1024) of d_out.
// block = 256 threads, one row per block, float4 per thread.
// ---------------------------------------------------------------------------
__global__ __launch_bounds__(256) void softmax_kernel(float* __restrict__ out){
    __shared__ float red[8];
    size_t row = blockIdx.x;
    int t = threadIdx.x, lane = t & 31, w = t >> 5;

    float4* p = ((float4*)out) + row*(NN/4) + t;
    float4 v = *p;

    // max reduce
    float m = fmaxf(fmaxf(v.x, v.y), fmaxf(v.z, v.w));
    #pragma unroll
    for (int o = 16; o; o >>= 1) m = fmaxf(m, __shfl_xor_sync(0xffffffffu, m, o));
    if (lane == 0) red[w] = m;
    __syncthreads();
    m = red[0];
    #pragma unroll
    for (int k = 1; k < 8; k++) m = fmaxf(m, red[k]);

    // exp + sum reduce
    v.x = ex2_fast((v.x - m)*LOG2E);
    v.y = ex2_fast((v.y - m)*LOG2E);
    v.z = ex2_fast((v.z - m)*LOG2E);
    v.w = ex2_fast((v.w - m)*LOG2E);
    float s = (v.x + v.y) + (v.z + v.w);
    #pragma unroll
    for (int o = 16; o; o >>= 1) s += __shfl_xor_sync(0xffffffffu, s, o);
    __syncthreads();                       // red[] reuse
    if (lane == 0) red[w] = s;
    __syncthreads();
    s = red[0];
    #pragma unroll
    for (int k = 1; k < 8; k++) s += red[k];

    float inv = 1.0f / s;
    v.x *= inv; v.y *= inv; v.z *= inv; v.w *= inv;
    *p = v;
}

// ---------------------------------------------------------------------------
extern "C" void kernel_launch(void* const* d_in, const int* in_sizes, int n_in,
                              void* d_out, int out_size){
    const float* x  = (const float*)d_in[0];
    const float* W1 = (const float*)d_in[1];
    const float* W2 = (const float*)d_in[2];
    const float* w3 = (const float*)d_in[3];
    float* out = (float*)d_out;

    proj_kernel<<<ROWS/2, 256>>>(x, W1, W2);
    logits_kernel<<<BN*(NN/IB), 256>>>(w3, out);
    softmax_kernel<<<(unsigned)BN*NN, 256>>>(out);
}

// round 6
// speedup vs baseline: 1.1374x; 1.1374x over previous
#include <cuda_runtime.h>
#include <cstddef>

#define BN 4
#define NN 1024
#define CC 64
#define ROWS (BN*NN)   // 4096
#define IB 8           // i-rows per logits block (one warp per i-row)
#define JC 128         // j chunk per smem tile
#define JH 512         // j per block (half of NN)

// precomputed tanh of projections (device globals: no allocation allowed)
__device__ float g_t1[ROWS*CC];
__device__ float g_t2[ROWS*CC];

__device__ __forceinline__ float tanh_fast(float x){
    float y; asm("tanh.approx.f32 %0, %1;" : "=f"(y) : "f"(x)); return y;
}
__device__ __forceinline__ float rcp_fast(float x){
    float y; asm("rcp.approx.f32 %0, %1;" : "=f"(y) : "f"(x)); return y;
}
__device__ __forceinline__ float ex2_fast(float x){
    float y; asm("ex2.approx.f32 %0, %1;" : "=f"(y) : "f"(x)); return y;
}
#define LOG2E 1.4426950408889634f

// ---------------------------------------------------------------------------
// Kernel 1: t1 = tanh(x @ W1^T), t2 = tanh(x @ W2^T)
// 16 rows per block: weights staged ONCE, x rows staged once, no loop syncs.
// ---------------------------------------------------------------------------
__global__ __launch_bounds__(256) void proj_kernel(const float* __restrict__ x,
                                                   const float* __restrict__ W1,
                                                   const float* __restrict__ W2){
    __shared__ float Ws[2][64][65];   // pad 65 -> bank = (d + c) % 32, conflict-free
    __shared__ float xs[16][64];
    int t = threadIdx.x;

    const float4* w1v = (const float4*)W1;
    const float4* w2v = (const float4*)W2;
    #pragma unroll
    for (int p = 0; p < 4; p++){
        int idx = p*256 + t;            // float4 index 0..1023
        int d = idx >> 4, c4 = (idx & 15) * 4;
        float4 v = w1v[idx];
        Ws[0][d][c4+0]=v.x; Ws[0][d][c4+1]=v.y; Ws[0][d][c4+2]=v.z; Ws[0][d][c4+3]=v.w;
        v = w2v[idx];
        Ws[1][d][c4+0]=v.x; Ws[1][d][c4+1]=v.y; Ws[1][d][c4+2]=v.z; Ws[1][d][c4+3]=v.w;
    }
    int row0 = blockIdx.x * 16;
    {   // stage all 16 x rows: 256 float4, one per thread
        int rl = t >> 4, c4 = (t & 15) * 4;
        float4 v = ((const float4*)(x + (size_t)(row0+rl)*CC))[t & 15];
        xs[rl][c4+0]=v.x; xs[rl][c4+1]=v.y; xs[rl][c4+2]=v.z; xs[rl][c4+3]=v.w;
    }
    __syncthreads();

    int m  = t >> 7;          // 0 -> t1, 1 -> t2
    int rr = (t >> 6) & 1;
    int d  = t & 63;
    float* dst = m ? g_t2 : g_t1;
    #pragma unroll
    for (int it = 0; it < 8; it++){
        int rl = it*2 + rr;
        float acc = 0.f;
        #pragma unroll
        for (int c = 0; c < 64; c++)
            acc = fmaf(xs[rl][c], Ws[m][d][c], acc);
        dst[(size_t)(row0+rl)*CC + d] = tanh_fast(acc);
    }
}

// ---------------------------------------------------------------------------
// Kernel 2: logits[b,i,j] = sum_c w3[c] * tanh(z1+z2)
//   via identity tanh(a+b) = (ta+tb)/(1+ta*tb):
//   val = (p[c] + w3[c]*t2) * rcp(1 + t1[c]*t2),  p[c] = w3[c]*t1[c]
// One MUFU.RCP (rt 8) per element instead of MUFU.TANH (rt ~16).
// grid = 4b x 128 ihalf x 2 jhalf = 1024 blocks; 8 warps, one i-row per warp,
// 4 j per lane; 4 tiles of JC=128 per block.
// ---------------------------------------------------------------------------
__global__ __launch_bounds__(256) void logits_kernel(const float* __restrict__ w3f,
                                                     float* __restrict__ out){
    __shared__ float t2s[CC][JC+1];
    __shared__ float t1s[IB][CC];
    __shared__ float ps [IB][CC];
    __shared__ float w3s[CC];

    int t = threadIdx.x;
    int lane = t & 31, il = t >> 5;       // warp = i-row
    int blk = blockIdx.x;
    int b  = blk >> 8;
    int ih = (blk >> 1) & 127;
    int jh = blk & 1;
    int i0 = ih * IB;

    if (t < 128){                         // t1 rows: 128 float4 = 8x64
        float4 v = ((const float4*)(g_t1 + ((size_t)b*NN + i0)*CC))[t];
        int ii = t >> 4, c4 = (t & 15) * 4;
        t1s[ii][c4+0]=v.x; t1s[ii][c4+1]=v.y; t1s[ii][c4+2]=v.z; t1s[ii][c4+3]=v.w;
    } else if (t < 144){                  // w3: 16 float4
        float4 v = ((const float4*)w3f)[t-128];
        int c4 = (t-128)*4;
        w3s[c4+0]=v.x; w3s[c4+1]=v.y; w3s[c4+2]=v.z; w3s[c4+3]=v.w;
    }
    __syncthreads();
    {   // ps = w3 * t1 (512 values, 2 per thread)
        float* t1f = &t1s[0][0];
        float* psf = &ps[0][0];
        psf[t]       = w3s[t & 63]        * t1f[t];
        psf[t + 256] = w3s[(t + 256)&63]  * t1f[t + 256];
    }

    const float* t2base = g_t2 + (size_t)b*NN*CC + (size_t)jh*JH*CC;
    int i = i0 + il;
    float* orowbase = out + ((size_t)b*NN + i)*NN + (size_t)jh*JH;

    for (int jc = 0; jc < JH/JC; jc++){
        __syncthreads();
        // stage t2 tile transposed: t2s[c][j], j in [jc*JC, jc*JC+JC)
        #pragma unroll
        for (int p = 0; p < (JC*CC/4)/256; p++){   // 8 float4 per thread
            int idx = p*256 + t;
            int j = idx >> 4, c4 = (idx & 15) * 4;
            float4 v = ((const float4*)(t2base + (size_t)(jc*JC + j)*CC))[idx & 15];
            t2s[c4+0][j]=v.x; t2s[c4+1][j]=v.y; t2s[c4+2][j]=v.z; t2s[c4+3][j]=v.w;
        }
        __syncthreads();

        float a0 = 0.f, a1 = 0.f, a2 = 0.f, a3 = 0.f;
        #pragma unroll
        for (int c = 0; c < CC; c++){
            float t1c = t1s[il][c];
            float pc  = ps [il][c];
            float w3c = w3s[c];
            float u0 = t2s[c][lane      ];
            float u1 = t2s[c][lane + 32 ];
            float u2 = t2s[c][lane + 64 ];
            float u3 = t2s[c][lane + 96 ];
            float r0 = rcp_fast(fmaf(t1c, u0, 1.0f));
            float r1 = rcp_fast(fmaf(t1c, u1, 1.0f));
            float r2 = rcp_fast(fmaf(t1c, u2, 1.0f));
            float r3 = rcp_fast(fmaf(t1c, u3, 1.0f));
            a0 = fmaf(fmaf(w3c, u0, pc), r0, a0);
            a1 = fmaf(fmaf(w3c, u1, pc), r1, a1);
            a2 = fmaf(fmaf(w3c, u2, pc), r2, a2);
            a3 = fmaf(fmaf(w3c, u3, pc), r3, a3);
        }
        float* orow = orowbase + jc*JC;
        orow[lane      ] = a0;
        orow[lane + 32 ] = a1;
        orow[lane + 64 ] = a2;
        orow[lane + 96 ] = a3;
    }
}

// ---------------------------------------------------------------------------
// Kernel 3: in-place row softmax over last dim (1024) of d_out.
// ---------------------------------------------------------------------------
__global__ __launch_bounds__(256) void softmax_kernel(float* __restrict__ out){
    __shared__ float red[8];
    size_t row = blockIdx.x;
    int t = threadIdx.x, lane = t & 31, w = t >> 5;

    float4* p = ((float4*)out) + row*(NN/4) + t;
    float4 v = *p;

    float m = fmaxf(fmaxf(v.x, v.y), fmaxf(v.z, v.w));
    #pragma unroll
    for (int o = 16; o; o >>= 1) m = fmaxf(m, __shfl_xor_sync(0xffffffffu, m, o));
    if (lane == 0) red[w] = m;
    __syncthreads();
    m = red[0];
    #pragma unroll
    for (int k = 1; k < 8; k++) m = fmaxf(m, red[k]);

    v.x = ex2_fast((v.x - m)*LOG2E);
    v.y = ex2_fast((v.y - m)*LOG2E);
    v.z = ex2_fast((v.z - m)*LOG2E);
    v.w = ex2_fast((v.w - m)*LOG2E);
    float s = (v.x + v.y) + (v.z + v.w);
    #pragma unroll
    for (int o = 16; o; o >>= 1) s += __shfl_xor_sync(0xffffffffu, s, o);
    __syncthreads();
    if (lane == 0) red[w] = s;
    __syncthreads();
    s = red[0];
    #pragma unroll
    for (int k = 1; k < 8; k++) s += red[k];

    float inv = 1.0f / s;
    v.x *= inv; v.y *= inv; v.z *= inv; v.w *= inv;
    *p = v;
}

// ---------------------------------------------------------------------------
extern "C" void kernel_launch(void* const* d_in, const int* in_sizes, int n_in,
                              void* d_out, int out_size){
    const float* x  = (const float*)d_in[0];
    const float* W1 = (const float*)d_in[1];
    const float* W2 = (const float*)d_in[2];
    const float* w3 = (const float*)d_in[3];
    float* out = (float*)d_out;

    proj_kernel<<<ROWS/16, 256>>>(x, W1, W2);
    logits_kernel<<<BN*128*2, 256>>>(w3, out);
    softmax_kernel<<<(unsigned)BN*NN, 256>>>(out);
}

// round 7
// speedup vs baseline: 1.3670x; 1.2019x over previous
#include <cuda_runtime.h>
#include <cstddef>

#define BN 4
#define NN 1024
#define CC 64
#define ROWS (BN*NN)   // 4096
#define IB 8           // i-rows per logits block (one warp per i-row)
#define JC 128         // j chunk per smem tile
#define JH 512         // j per block (half of NN)

// precomputed tanh of projections (device globals: no allocation allowed)
__device__ float g_t1[ROWS*CC];
__device__ float g_t2[ROWS*CC];

__device__ __forceinline__ float tanh_fast(float x){
    float y; asm("tanh.approx.f32 %0, %1;" : "=f"(y) : "f"(x)); return y;
}
__device__ __forceinline__ float rcp_fast(float x){
    float y; asm("rcp.approx.f32 %0, %1;" : "=f"(y) : "f"(x)); return y;
}
__device__ __forceinline__ float ex2_fast(float x){
    float y; asm("ex2.approx.f32 %0, %1;" : "=f"(y) : "f"(x)); return y;
}
#define LOG2E 1.4426950408889634f

// ---------------------------------------------------------------------------
// Kernel 1: t1 = tanh(x @ W1^T), t2 = tanh(x @ W2^T)
// 8 rows per block (grid 512): 4 outputs/thread -> low regs, better occupancy.
// ---------------------------------------------------------------------------
__global__ __launch_bounds__(256) void proj_kernel(const float* __restrict__ x,
                                                   const float* __restrict__ W1,
                                                   const float* __restrict__ W2){
    __shared__ float Ws[2][64][65];   // pad 65 -> conflict-free
    __shared__ float xs[8][64];
    int t = threadIdx.x;

    const float4* w1v = (const float4*)W1;
    const float4* w2v = (const float4*)W2;
    #pragma unroll
    for (int p = 0; p < 4; p++){
        int idx = p*256 + t;            // float4 index 0..1023
        int d = idx >> 4, c4 = (idx & 15) * 4;
        float4 v = w1v[idx];
        Ws[0][d][c4+0]=v.x; Ws[0][d][c4+1]=v.y; Ws[0][d][c4+2]=v.z; Ws[0][d][c4+3]=v.w;
        v = w2v[idx];
        Ws[1][d][c4+0]=v.x; Ws[1][d][c4+1]=v.y; Ws[1][d][c4+2]=v.z; Ws[1][d][c4+3]=v.w;
    }
    int row0 = blockIdx.x * 8;
    if (t < 128){                       // stage 8 x rows: 128 float4
        int rl = t >> 4, c4 = (t & 15) * 4;
        float4 v = ((const float4*)(x + (size_t)(row0+rl)*CC))[t & 15];
        xs[rl][c4+0]=v.x; xs[rl][c4+1]=v.y; xs[rl][c4+2]=v.z; xs[rl][c4+3]=v.w;
    }
    __syncthreads();

    int m  = t >> 7;          // 0 -> t1, 1 -> t2
    int rr = (t >> 6) & 1;
    int d  = t & 63;
    float* dst = m ? g_t2 : g_t1;
    #pragma unroll
    for (int it = 0; it < 4; it++){
        int rl = it*2 + rr;
        float acc = 0.f;
        #pragma unroll
        for (int c = 0; c < 64; c++)
            acc = fmaf(xs[rl][c], Ws[m][d][c], acc);
        dst[(size_t)(row0+rl)*CC + d] = tanh_fast(acc);
    }
}

// ---------------------------------------------------------------------------
// Kernel 2: logits[b,i,j] = sum_c w3[c]*tanh(z1+z2)
//   tanh(a+b) = (ta+tb)/(1+ta*tb); per-c term = N_c/D_c with
//   N_c = p_c + w3_c*u,  D_c = 1 + t1_c*u,  p_c = w3_c*t1_c.
//   CHANNEL PAIRING: N1/D1 + N2/D2 = (N1*D2 + N2*D1)*rcp(D1*D2)
//   -> ONE MUFU.RCP per TWO channels (halves MUFU load; exact algebra).
// ---------------------------------------------------------------------------
__global__ __launch_bounds__(256) void logits_kernel(const float* __restrict__ w3f,
                                                     float* __restrict__ out){
    __shared__ float t2s[CC][JC+1];
    __shared__ float t1s[IB][CC];
    __shared__ float ps [IB][CC];
    __shared__ float w3s[CC];

    int t = threadIdx.x;
    int lane = t & 31, il = t >> 5;       // warp = i-row
    int blk = blockIdx.x;
    int b  = blk >> 8;
    int ih = (blk >> 1) & 127;
    int jh = blk & 1;
    int i0 = ih * IB;

    if (t < 128){                         // t1 rows: 128 float4 = 8x64
        float4 v = ((const float4*)(g_t1 + ((size_t)b*NN + i0)*CC))[t];
        int ii = t >> 4, c4 = (t & 15) * 4;
        t1s[ii][c4+0]=v.x; t1s[ii][c4+1]=v.y; t1s[ii][c4+2]=v.z; t1s[ii][c4+3]=v.w;
    } else if (t < 144){                  // w3: 16 float4
        float4 v = ((const float4*)w3f)[t-128];
        int c4 = (t-128)*4;
        w3s[c4+0]=v.x; w3s[c4+1]=v.y; w3s[c4+2]=v.z; w3s[c4+3]=v.w;
    }
    __syncthreads();
    {   // ps = w3 * t1 (512 values, 2 per thread)
        float* t1f = &t1s[0][0];
        float* psf = &ps[0][0];
        psf[t]       = w3s[t & 63]        * t1f[t];
        psf[t + 256] = w3s[(t + 256)&63]  * t1f[t + 256];
    }

    const float* t2base = g_t2 + (size_t)b*NN*CC + (size_t)jh*JH*CC;
    int i = i0 + il;
    float* orowbase = out + ((size_t)b*NN + i)*NN + (size_t)jh*JH;

    for (int jc = 0; jc < JH/JC; jc++){
        __syncthreads();
        // stage t2 tile transposed: t2s[c][j]
        #pragma unroll
        for (int p = 0; p < (JC*CC/4)/256; p++){   // 8 float4 per thread
            int idx = p*256 + t;
            int j = idx >> 4, c4 = (idx & 15) * 4;
            float4 v = ((const float4*)(t2base + (size_t)(jc*JC + j)*CC))[idx & 15];
            t2s[c4+0][j]=v.x; t2s[c4+1][j]=v.y; t2s[c4+2][j]=v.z; t2s[c4+3][j]=v.w;
        }
        __syncthreads();

        float a0 = 0.f, a1 = 0.f, a2 = 0.f, a3 = 0.f;
        #pragma unroll
        for (int c = 0; c < CC; c += 2){
            float t1a = t1s[il][c],   t1b = t1s[il][c+1];
            float pa  = ps [il][c],   pb  = ps [il][c+1];
            float wa  = w3s[c],       wb  = w3s[c+1];

            {   float ua = t2s[c][lane],        ub = t2s[c+1][lane];
                float D1 = fmaf(t1a, ua, 1.f),  N1 = fmaf(wa, ua, pa);
                float D2 = fmaf(t1b, ub, 1.f),  N2 = fmaf(wb, ub, pb);
                float num = fmaf(N1, D2, N2*D1);
                a0 = fmaf(num, rcp_fast(D1*D2), a0); }
            {   float ua = t2s[c][lane+32],     ub = t2s[c+1][lane+32];
                float D1 = fmaf(t1a, ua, 1.f),  N1 = fmaf(wa, ua, pa);
                float D2 = fmaf(t1b, ub, 1.f),  N2 = fmaf(wb, ub, pb);
                float num = fmaf(N1, D2, N2*D1);
                a1 = fmaf(num, rcp_fast(D1*D2), a1); }
            {   float ua = t2s[c][lane+64],     ub = t2s[c+1][lane+64];
                float D1 = fmaf(t1a, ua, 1.f),  N1 = fmaf(wa, ua, pa);
                float D2 = fmaf(t1b, ub, 1.f),  N2 = fmaf(wb, ub, pb);
                float num = fmaf(N1, D2, N2*D1);
                a2 = fmaf(num, rcp_fast(D1*D2), a2); }
            {   float ua = t2s[c][lane+96],     ub = t2s[c+1][lane+96];
                float D1 = fmaf(t1a, ua, 1.f),  N1 = fmaf(wa, ua, pa);
                float D2 = fmaf(t1b, ub, 1.f),  N2 = fmaf(wb, ub, pb);
                float num = fmaf(N1, D2, N2*D1);
                a3 = fmaf(num, rcp_fast(D1*D2), a3); }
        }
        float* orow = orowbase + jc*JC;
        orow[lane      ] = a0;
        orow[lane + 32 ] = a1;
        orow[lane + 64 ] = a2;
        orow[lane + 96 ] = a3;
    }
}

// ---------------------------------------------------------------------------
// Kernel 3: in-place row softmax over last dim (1024) of d_out.
// ---------------------------------------------------------------------------
__global__ __launch_bounds__(256) void softmax_kernel(float* __restrict__ out){
    __shared__ float red[8];
    size_t row = blockIdx.x;
    int t = threadIdx.x, lane = t & 31, w = t >> 5;

    float4* p = ((float4*)out) + row*(NN/4) + t;
    float4 v = *p;

    float m = fmaxf(fmaxf(v.x, v.y), fmaxf(v.z, v.w));
    #pragma unroll
    for (int o = 16; o; o >>= 1) m = fmaxf(m, __shfl_xor_sync(0xffffffffu, m, o));
    if (lane == 0) red[w] = m;
    __syncthreads();
    m = red[0];
    #pragma unroll
    for (int k = 1; k < 8; k++) m = fmaxf(m, red[k]);

    v.x = ex2_fast((v.x - m)*LOG2E);
    v.y = ex2_fast((v.y - m)*LOG2E);
    v.z = ex2_fast((v.z - m)*LOG2E);
    v.w = ex2_fast((v.w - m)*LOG2E);
    float s = (v.x + v.y) + (v.z + v.w);
    #pragma unroll
    for (int o = 16; o; o >>= 1) s += __shfl_xor_sync(0xffffffffu, s, o);
    __syncthreads();
    if (lane == 0) red[w] = s;
    __syncthreads();
    s = red[0];
    #pragma unroll
    for (int k = 1; k < 8; k++) s += red[k];

    float inv = 1.0f / s;
    v.x *= inv; v.y *= inv; v.z *= inv; v.w *= inv;
    *p = v;
}

// ---------------------------------------------------------------------------
extern "C" void kernel_launch(void* const* d_in, const int* in_sizes, int n_in,
                              void* d_out, int out_size){
    const float* x  = (const float*)d_in[0];
    const float* W1 = (const float*)d_in[1];
    const float* W2 = (const float*)d_in[2];
    const float* w3 = (const float*)d_in[3];
    float* out = (float*)d_out;

    proj_kernel<<<ROWS/8, 256>>>(x, W1, W2);
    logits_kernel<<<BN*128*2, 256>>>(w3, out);
    softmax_kernel<<<(unsigned)BN*NN, 256>>>(out);
}

// round 8
// speedup vs baseline: 1.6008x; 1.1711x over previous
#include <cuda_runtime.h>
#include <cstddef>

#define BN 4
#define NN 1024
#define CC 64
#define ROWS (BN*NN)   // 4096
#define IB 8           // i-rows per logits block (one warp per i-row)
#define JC 128         // j chunk per smem tile
#define JH 512         // j per block (half of NN)

typedef unsigned long long ull;

// precomputed tanh of projections (device globals: no allocation allowed)
__device__ float g_t1[ROWS*CC];
__device__ float g_t2[ROWS*CC];

__device__ __forceinline__ float tanh_fast(float x){
    float y; asm("tanh.approx.f32 %0, %1;" : "=f"(y) : "f"(x)); return y;
}
__device__ __forceinline__ float rcp_fast(float x){
    float y; asm("rcp.approx.f32 %0, %1;" : "=f"(y) : "f"(x)); return y;
}
__device__ __forceinline__ float ex2_fast(float x){
    float y; asm("ex2.approx.f32 %0, %1;" : "=f"(y) : "f"(x)); return y;
}
__device__ __forceinline__ ull fma2(ull a, ull b, ull c){
    ull d; asm("fma.rn.f32x2 %0, %1, %2, %3;" : "=l"(d) : "l"(a), "l"(b), "l"(c)); return d;
}
__device__ __forceinline__ ull mul2(ull a, ull b){
    ull d; asm("mul.rn.f32x2 %0, %1, %2;" : "=l"(d) : "l"(a), "l"(b)); return d;
}
__device__ __forceinline__ ull rcp2(ull a){
    float lo, hi;
    asm("mov.b64 {%0, %1}, %2;" : "=f"(lo), "=f"(hi) : "l"(a));
    lo = rcp_fast(lo); hi = rcp_fast(hi);
    ull d; asm("mov.b64 %0, {%1, %2};" : "=l"(d) : "f"(lo), "f"(hi)); return d;
}
#define ONE2 0x3F8000003F800000ULL
#define LOG2E 1.4426950408889634f

// ---------------------------------------------------------------------------
// Kernel 1: t1 = tanh(x @ W1^T), t2 = tanh(x @ W2^T)
// 16 rows per block (R6 version, measured 7.8us).
// ---------------------------------------------------------------------------
__global__ __launch_bounds__(256) void proj_kernel(const float* __restrict__ x,
                                                   const float* __restrict__ W1,
                                                   const float* __restrict__ W2){
    __shared__ float Ws[2][64][65];
    __shared__ float xs[16][64];
    int t = threadIdx.x;

    const float4* w1v = (const float4*)W1;
    const float4* w2v = (const float4*)W2;
    #pragma unroll
    for (int p = 0; p < 4; p++){
        int idx = p*256 + t;
        int d = idx >> 4, c4 = (idx & 15) * 4;
        float4 v = w1v[idx];
        Ws[0][d][c4+0]=v.x; Ws[0][d][c4+1]=v.y; Ws[0][d][c4+2]=v.z; Ws[0][d][c4+3]=v.w;
        v = w2v[idx];
        Ws[1][d][c4+0]=v.x; Ws[1][d][c4+1]=v.y; Ws[1][d][c4+2]=v.z; Ws[1][d][c4+3]=v.w;
    }
    int row0 = blockIdx.x * 16;
    {
        int rl = t >> 4, c4 = (t & 15) * 4;
        float4 v = ((const float4*)(x + (size_t)(row0+rl)*CC))[t & 15];
        xs[rl][c4+0]=v.x; xs[rl][c4+1]=v.y; xs[rl][c4+2]=v.z; xs[rl][c4+3]=v.w;
    }
    __syncthreads();

    int m  = t >> 7;
    int rr = (t >> 6) & 1;
    int d  = t & 63;
    float* dst = m ? g_t2 : g_t1;
    #pragma unroll
    for (int it = 0; it < 8; it++){
        int rl = it*2 + rr;
        float acc = 0.f;
        #pragma unroll
        for (int c = 0; c < 64; c++)
            acc = fmaf(xs[rl][c], Ws[m][d][c], acc);
        dst[(size_t)(row0+rl)*CC + d] = tanh_fast(acc);
    }
}

// ---------------------------------------------------------------------------
// Kernel 2: logits via tanh addition identity + 4-channel common denominator
// + packed f32x2 over j-pairs.
//   per channel: N_c = w_c*(u + t1_c), D_c = 1 + t1_c*u
//   4-ch combine: sum = (N12*D34 + N34*D12) * rcp(D12*D34)
//   -> 1 RCP / 4 channels, all FMAs packed 2-wide over (j, j+1).
// ---------------------------------------------------------------------------
__global__ __launch_bounds__(256) void logits_kernel(const float* __restrict__ w3f,
                                                     float* __restrict__ out){
    __shared__ float  t2s[CC][JC+2];   // transposed tile, 8B-aligned rows
    __shared__ float2 t1d[IB][CC];     // duplicated (t1,t1)
    __shared__ float2 psd[IB][CC];     // duplicated (w3*t1, w3*t1)
    __shared__ float2 w3d[CC];         // duplicated (w3,w3)

    int t = threadIdx.x;
    int lane = t & 31, il = t >> 5;    // warp = i-row
    int blk = blockIdx.x;
    int b  = blk >> 8;
    int ih = (blk >> 1) & 127;
    int jh = blk & 1;
    int i0 = ih * IB;

    if (t < 128){                      // t1 rows + ps: 128 float4 = 8x64
        float4 v = ((const float4*)(g_t1 + ((size_t)b*NN + i0)*CC))[t];
        float4 w = ((const float4*)w3f)[t & 15];
        int ii = t >> 4, c4 = (t & 15) * 4;
        t1d[ii][c4+0] = make_float2(v.x, v.x);  psd[ii][c4+0] = make_float2(w.x*v.x, w.x*v.x);
        t1d[ii][c4+1] = make_float2(v.y, v.y);  psd[ii][c4+1] = make_float2(w.y*v.y, w.y*v.y);
        t1d[ii][c4+2] = make_float2(v.z, v.z);  psd[ii][c4+2] = make_float2(w.z*v.z, w.z*v.z);
        t1d[ii][c4+3] = make_float2(v.w, v.w);  psd[ii][c4+3] = make_float2(w.w*v.w, w.w*v.w);
    } else if (t < 144){
        float4 w = ((const float4*)w3f)[t-128];
        int c4 = (t-128)*4;
        w3d[c4+0] = make_float2(w.x, w.x);
        w3d[c4+1] = make_float2(w.y, w.y);
        w3d[c4+2] = make_float2(w.z, w.z);
        w3d[c4+3] = make_float2(w.w, w.w);
    }

    const float* t2base = g_t2 + (size_t)b*NN*CC + (size_t)jh*JH*CC;
    int i = i0 + il;
    float* orowbase = out + ((size_t)b*NN + i)*NN + (size_t)jh*JH;
    int w = t >> 5;

    for (int jc = 0; jc < JH/JC; jc++){
        __syncthreads();
        // stage t2 tile transposed: warp covers 32 c at one j (2-way STS max)
        #pragma unroll
        for (int k = 0; k < 16; k++){
            int j = k*8 + w;
            const float* grow = t2base + (size_t)(jc*JC + j)*CC;
            float v0 = grow[lane];
            float v1 = grow[lane + 32];
            t2s[lane     ][j] = v0;
            t2s[lane + 32][j] = v1;
        }
        __syncthreads();

        ull acc0 = 0ULL, acc1 = 0ULL;   // packed (0.f, 0.f)
        int jj0 = 2*lane, jj1 = 2*lane + 64;
        #pragma unroll
        for (int c = 0; c < CC; c += 4){
            ull t1a = *(const ull*)&t1d[il][c+0];
            ull t1b = *(const ull*)&t1d[il][c+1];
            ull t1c = *(const ull*)&t1d[il][c+2];
            ull t1e = *(const ull*)&t1d[il][c+3];
            ull pa  = *(const ull*)&psd[il][c+0];
            ull pb  = *(const ull*)&psd[il][c+1];
            ull pc  = *(const ull*)&psd[il][c+2];
            ull pe  = *(const ull*)&psd[il][c+3];
            ull wa  = *(const ull*)&w3d[c+0];
            ull wb  = *(const ull*)&w3d[c+1];
            ull wc  = *(const ull*)&w3d[c+2];
            ull we  = *(const ull*)&w3d[c+3];
            {
                ull u0 = *(const ull*)&t2s[c+0][jj0];
                ull u1 = *(const ull*)&t2s[c+1][jj0];
                ull u2 = *(const ull*)&t2s[c+2][jj0];
                ull u3 = *(const ull*)&t2s[c+3][jj0];
                ull D0 = fma2(t1a,u0,ONE2), N0 = fma2(wa,u0,pa);
                ull D1 = fma2(t1b,u1,ONE2), N1 = fma2(wb,u1,pb);
                ull D2 = fma2(t1c,u2,ONE2), N2 = fma2(wc,u2,pc);
                ull D3 = fma2(t1e,u3,ONE2), N3 = fma2(we,u3,pe);
                ull N01 = fma2(N1, D0, mul2(N0, D1));
                ull D01 = mul2(D0, D1);
                ull N23 = fma2(N3, D2, mul2(N2, D3));
                ull D23 = mul2(D2, D3);
                ull Nf  = fma2(N23, D01, mul2(N01, D23));
                ull Df  = mul2(D01, D23);
                acc0 = fma2(Nf, rcp2(Df), acc0);
            }
            {
                ull u0 = *(const ull*)&t2s[c+0][jj1];
                ull u1 = *(const ull*)&t2s[c+1][jj1];
                ull u2 = *(const ull*)&t2s[c+2][jj1];
                ull u3 = *(const ull*)&t2s[c+3][jj1];
                ull D0 = fma2(t1a,u0,ONE2), N0 = fma2(wa,u0,pa);
                ull D1 = fma2(t1b,u1,ONE2), N1 = fma2(wb,u1,pb);
                ull D2 = fma2(t1c,u2,ONE2), N2 = fma2(wc,u2,pc);
                ull D3 = fma2(t1e,u3,ONE2), N3 = fma2(we,u3,pe);
                ull N01 = fma2(N1, D0, mul2(N0, D1));
                ull D01 = mul2(D0, D1);
                ull N23 = fma2(N3, D2, mul2(N2, D3));
                ull D23 = mul2(D2, D3);
                ull Nf  = fma2(N23, D01, mul2(N01, D23));
                ull Df  = mul2(D01, D23);
                acc1 = fma2(Nf, rcp2(Df), acc1);
            }
        }
        float* orow = orowbase + jc*JC;
        *(ull*)(orow + jj0) = acc0;       // j = 2lane, 2lane+1
        *(ull*)(orow + jj1) = acc1;       // j = 64+2lane, 64+2lane+1
    }
}

// ---------------------------------------------------------------------------
// Kernel 3: in-place row softmax over last dim (1024) of d_out.
// ---------------------------------------------------------------------------
__global__ __launch_bounds__(256) void softmax_kernel(float* __restrict__ out){
    __shared__ float red[8];
    size_t row = blockIdx.x;
    int t = threadIdx.x, lane = t & 31, w = t >> 5;

    float4* p = ((float4*)out) + row*(NN/4) + t;
    float4 v = *p;

    float m = fmaxf(fmaxf(v.x, v.y), fmaxf(v.z, v.w));
    #pragma unroll
    for (int o = 16; o; o >>= 1) m = fmaxf(m, __shfl_xor_sync(0xffffffffu, m, o));
    if (lane == 0) red[w] = m;
    __syncthreads();
    m = red[0];
    #pragma unroll
    for (int k = 1; k < 8; k++) m = fmaxf(m, red[k]);

    v.x = ex2_fast((v.x - m)*LOG2E);
    v.y = ex2_fast((v.y - m)*LOG2E);
    v.z = ex2_fast((v.z - m)*LOG2E);
    v.w = ex2_fast((v.w - m)*LOG2E);
    float s = (v.x + v.y) + (v.z + v.w);
    #pragma unroll
    for (int o = 16; o; o >>= 1) s += __shfl_xor_sync(0xffffffffu, s, o);
    __syncthreads();
    if (lane == 0) red[w] = s;
    __syncthreads();
    s = red[0];
    #pragma unroll
    for (int k = 1; k < 8; k++) s += red[k];

    float inv = 1.0f / s;
    v.x *= inv; v.y *= inv; v.z *= inv; v.w *= inv;
    *p = v;
}

// ---------------------------------------------------------------------------
extern "C" void kernel_launch(void* const* d_in, const int* in_sizes, int n_in,
                              void* d_out, int out_size){
    const float* x  = (const float*)d_in[0];
    const float* W1 = (const float*)d_in[1];
    const float* W2 = (const float*)d_in[2];
    const float* w3 = (const float*)d_in[3];
    float* out = (float*)d_out;

    proj_kernel<<<ROWS/16, 256>>>(x, W1, W2);
    logits_kernel<<<BN*128*2, 256>>>(w3, out);
    softmax_kernel<<<(unsigned)BN*NN, 256>>>(out);
}

// round 9
// speedup vs baseline: 1.8279x; 1.1419x over previous
#include <cuda_runtime.h>
#include <cstddef>

#define BN 4
#define NN 1024
#define CC 64
#define ROWS (BN*NN)   // 4096
#define IB 8           // i-rows per logits block (one warp per i-row)
#define JC 128         // j per logits block

typedef unsigned long long ull;

// device scratch (no allocation allowed)
__device__ float g_A [ROWS*CC];          // e^{2*z1}, clamped
__device__ float g_u [ROWS*CC];          // e^{2*z2}, clamped (j-major)
__device__ float g_uT[BN*CC*NN];         // transposed: [b][c][j]

__device__ __forceinline__ float rcp_fast(float x){
    float y; asm("rcp.approx.f32 %0, %1;" : "=f"(y) : "f"(x)); return y;
}
__device__ __forceinline__ float ex2_fast(float x){
    float y; asm("ex2.approx.f32 %0, %1;" : "=f"(y) : "f"(x)); return y;
}
__device__ __forceinline__ ull fma2(ull a, ull b, ull c){
    ull d; asm("fma.rn.f32x2 %0, %1, %2, %3;" : "=l"(d) : "l"(a), "l"(b), "l"(c)); return d;
}
__device__ __forceinline__ ull mul2(ull a, ull b){
    ull d; asm("mul.rn.f32x2 %0, %1, %2;" : "=l"(d) : "l"(a), "l"(b)); return d;
}
__device__ __forceinline__ ull rcp2(ull a){
    float lo, hi;
    asm("mov.b64 {%0, %1}, %2;" : "=f"(lo), "=f"(hi) : "l"(a));
    lo = rcp_fast(lo); hi = rcp_fast(hi);
    ull d; asm("mov.b64 %0, {%1, %2};" : "=l"(d) : "f"(lo), "f"(hi)); return d;
}
__device__ __forceinline__ ull pk2(float f){
    unsigned u = __float_as_uint(f);
    return (ull)u | ((ull)u << 32);
}
#define ONE2 0x3F8000003F800000ULL
#define LOG2E 1.4426950408889634f
#define TWO_LOG2E 2.8853900817779268f
#define EXP_CAP 3.0e4f

// ---------------------------------------------------------------------------
// Kernel 1: A = clamp(e^{2*(x@W1^T)}), u = clamp(e^{2*(x@W2^T)})
// ---------------------------------------------------------------------------
__global__ __launch_bounds__(256) void proj_kernel(const float* __restrict__ x,
                                                   const float* __restrict__ W1,
                                                   const float* __restrict__ W2){
    __shared__ float Ws[2][64][65];
    __shared__ float xs[16][64];
    int t = threadIdx.x;

    const float4* w1v = (const float4*)W1;
    const float4* w2v = (const float4*)W2;
    #pragma unroll
    for (int p = 0; p < 4; p++){
        int idx = p*256 + t;
        int d = idx >> 4, c4 = (idx & 15) * 4;
        float4 v = w1v[idx];
        Ws[0][d][c4+0]=v.x; Ws[0][d][c4+1]=v.y; Ws[0][d][c4+2]=v.z; Ws[0][d][c4+3]=v.w;
        v = w2v[idx];
        Ws[1][d][c4+0]=v.x; Ws[1][d][c4+1]=v.y; Ws[1][d][c4+2]=v.z; Ws[1][d][c4+3]=v.w;
    }
    int row0 = blockIdx.x * 16;
    {
        int rl = t >> 4, c4 = (t & 15) * 4;
        float4 v = ((const float4*)(x + (size_t)(row0+rl)*CC))[t & 15];
        xs[rl][c4+0]=v.x; xs[rl][c4+1]=v.y; xs[rl][c4+2]=v.z; xs[rl][c4+3]=v.w;
    }
    __syncthreads();

    int m  = t >> 7;          // 0 -> A, 1 -> u
    int rr = (t >> 6) & 1;
    int d  = t & 63;
    float* dst = m ? g_u : g_A;
    #pragma unroll
    for (int it = 0; it < 8; it++){
        int rl = it*2 + rr;
        float acc = 0.f;
        #pragma unroll
        for (int c = 0; c < 64; c++)
            acc = fmaf(xs[rl][c], Ws[m][d][c], acc);
        float e = ex2_fast(acc * TWO_LOG2E);
        dst[(size_t)(row0+rl)*CC + d] = fminf(e, EXP_CAP);
    }
}

// ---------------------------------------------------------------------------
// Kernel 1b: transpose g_u [b][j][c] -> g_uT [b][c][j]
// ---------------------------------------------------------------------------
__global__ __launch_bounds__(256) void transpose_kernel(){
    __shared__ float ts[32][65];
    int t = threadIdx.x;
    int blk = blockIdx.x;           // 128
    int b = blk >> 5, j0 = (blk & 31) * 32;
    const float* src = g_u + ((size_t)b*NN + j0)*CC;
    #pragma unroll
    for (int k = 0; k < 2; k++){
        int idx = k*256 + t;        // 0..511 float4s
        int jr = idx >> 4, c4 = (idx & 15)*4;
        float4 v = *(const float4*)(src + jr*CC + c4);
        ts[jr][c4+0]=v.x; ts[jr][c4+1]=v.y; ts[jr][c4+2]=v.z; ts[jr][c4+3]=v.w;
    }
    __syncthreads();
    float* dst = g_uT + (size_t)b*CC*NN + j0;
    #pragma unroll
    for (int k = 0; k < 8; k++){
        int idx = k*256 + t;        // 0..2047
        int c = idx >> 5, jr = idx & 31;
        dst[(size_t)c*NN + jr] = ts[jr][c];
    }
}

// ---------------------------------------------------------------------------
// Kernel 2: logits[b,i,j] = S + sum_c w'_c / D_c,
//   D_c = 1 + A[i,c]*u[j,c],  w' = -2*w3,  S = sum w3.
//   (tanh(a+b) = 1 - 2/(1+e^{2a}e^{2b}); numerators are CONSTANT -> 1 FMA/term
//    at leaves, 4-channel common-denominator tree -> 1 RCP / 4 channels.)
// grid = 4b x 128ih x 8jt = 4096 blocks; 8 warps, one i-row per warp,
// 4 contiguous j per lane, all smem accesses conflict-free.
// ---------------------------------------------------------------------------
__global__ __launch_bounds__(256) void logits_kernel(const float* __restrict__ w3f,
                                                     float* __restrict__ out){
    __shared__ float      ut[CC][JC];     // 32KB, row = 512B (16B aligned)
    __shared__ ulonglong2 aw[IB][CC];     // (A,A | w',w') 8KB
    __shared__ float      w3lin[CC];

    int t = threadIdx.x;
    int lane = t & 31, il = t >> 5;       // warp = i-row
    int blk = blockIdx.x;
    int b  = blk >> 10;
    int ih = (blk >> 3) & 127;
    int jt = blk & 7;
    int i0 = ih * IB;
    int j0 = jt * JC;

    // stage u tile [64][128] from transposed gmem: fully coalesced, no conflicts
    const float* uTbase = g_uT + (size_t)b*CC*NN + j0;
    #pragma unroll
    for (int k = 0; k < 8; k++){
        int idx = k*256 + t;              // 0..2047 float4s
        int c = idx >> 5, j4 = idx & 31;
        float4 v = *(const float4*)(uTbase + (size_t)c*NN + 4*j4);
        *(float4*)&ut[c][4*j4] = v;
    }
    // stage (A, w') tables
    if (t < 128){
        int ii = t >> 4, c4 = (t & 15) * 4;
        float4 a4 = ((const float4*)(g_A + ((size_t)b*NN + i0 + ii)*CC))[t & 15];
        float4 w4 = ((const float4*)w3f)[t & 15];
        aw[ii][c4+0] = make_ulonglong2(pk2(a4.x), pk2(-2.0f*w4.x));
        aw[ii][c4+1] = make_ulonglong2(pk2(a4.y), pk2(-2.0f*w4.y));
        aw[ii][c4+2] = make_ulonglong2(pk2(a4.z), pk2(-2.0f*w4.z));
        aw[ii][c4+3] = make_ulonglong2(pk2(a4.w), pk2(-2.0f*w4.w));
    } else if (t < 192){
        w3lin[t-128] = w3f[t-128];
    }
    __syncthreads();

    float S = 0.f;
    #pragma unroll
    for (int c = 0; c < CC; c++) S += w3lin[c];

    int jb = 4*lane;
    ull acc0 = pk2(S);    // j = jb, jb+1
    ull acc1 = pk2(S);    // j = jb+2, jb+3

    #pragma unroll
    for (int g = 0; g < 16; g++){
        int c = g*4;
        ulonglong2 aw0 = aw[il][c+0];
        ulonglong2 aw1 = aw[il][c+1];
        ulonglong2 aw2 = aw[il][c+2];
        ulonglong2 aw3 = aw[il][c+3];
        ulonglong2 U0 = *(const ulonglong2*)&ut[c+0][jb];
        ulonglong2 U1 = *(const ulonglong2*)&ut[c+1][jb];
        ulonglong2 U2 = *(const ulonglong2*)&ut[c+2][jb];
        ulonglong2 U3 = *(const ulonglong2*)&ut[c+3][jb];
        {   // j pair (jb, jb+1)
            ull D0 = fma2(aw0.x, U0.x, ONE2);
            ull D1 = fma2(aw1.x, U1.x, ONE2);
            ull D2 = fma2(aw2.x, U2.x, ONE2);
            ull D3 = fma2(aw3.x, U3.x, ONE2);
            ull n01 = fma2(aw0.y, D1, mul2(aw1.y, D0));
            ull d01 = mul2(D0, D1);
            ull n23 = fma2(aw2.y, D3, mul2(aw3.y, D2));
            ull d23 = mul2(D2, D3);
            ull nf  = fma2(n01, d23, mul2(n23, d01));
            ull df  = mul2(d01, d23);
            acc0 = fma2(nf, rcp2(df), acc0);
        }
        {   // j pair (jb+2, jb+3)
            ull D0 = fma2(aw0.x, U0.y, ONE2);
            ull D1 = fma2(aw1.x, U1.y, ONE2);
            ull D2 = fma2(aw2.x, U2.y, ONE2);
            ull D3 = fma2(aw3.x, U3.y, ONE2);
            ull n01 = fma2(aw0.y, D1, mul2(aw1.y, D0));
            ull d01 = mul2(D0, D1);
            ull n23 = fma2(aw2.y, D3, mul2(aw3.y, D2));
            ull d23 = mul2(D2, D3);
            ull nf  = fma2(n01, d23, mul2(n23, d01));
            ull df  = mul2(d01, d23);
            acc1 = fma2(nf, rcp2(df), acc1);
        }
    }
    float* orow = out + ((size_t)(b*NN + i0 + il))*NN + j0;
    *(ulonglong2*)(orow + jb) = make_ulonglong2(acc0, acc1);
}

// ---------------------------------------------------------------------------
// Kernel 3: in-place row softmax over last dim (1024) of d_out.
// ---------------------------------------------------------------------------
__global__ __launch_bounds__(256) void softmax_kernel(float* __restrict__ out){
    __shared__ float red[8];
    size_t row = blockIdx.x;
    int t = threadIdx.x, lane = t & 31, w = t >> 5;

    float4* p = ((float4*)out) + row*(NN/4) + t;
    float4 v = *p;

    float m = fmaxf(fmaxf(v.x, v.y), fmaxf(v.z, v.w));
    #pragma unroll
    for (int o = 16; o; o >>= 1) m = fmaxf(m, __shfl_xor_sync(0xffffffffu, m, o));
    if (lane == 0) red[w] = m;
    __syncthreads();
    m = red[0];
    #pragma unroll
    for (int k = 1; k < 8; k++) m = fmaxf(m, red[k]);

    v.x = ex2_fast((v.x - m)*LOG2E);
    v.y = ex2_fast((v.y - m)*LOG2E);
    v.z = ex2_fast((v.z - m)*LOG2E);
    v.w = ex2_fast((v.w - m)*LOG2E);
    float s = (v.x + v.y) + (v.z + v.w);
    #pragma unroll
    for (int o = 16; o; o >>= 1) s += __shfl_xor_sync(0xffffffffu, s, o);
    __syncthreads();
    if (lane == 0) red[w] = s;
    __syncthreads();
    s = red[0];
    #pragma unroll
    for (int k = 1; k < 8; k++) s += red[k];

    float inv = 1.0f / s;
    v.x *= inv; v.y *= inv; v.z *= inv; v.w *= inv;
    *p = v;
}

// ---------------------------------------------------------------------------
extern "C" void kernel_launch(void* const* d_in, const int* in_sizes, int n_in,
                              void* d_out, int out_size){
    const float* x  = (const float*)d_in[0];
    const float* W1 = (const float*)d_in[1];
    const float* W2 = (const float*)d_in[2];
    const float* w3 = (const float*)d_in[3];
    float* out = (float*)d_out;

    proj_kernel<<<ROWS/16, 256>>>(x, W1, W2);
    transpose_kernel<<<BN*32, 256>>>();
    logits_kernel<<<BN*128*8, 256>>>(w3, out);
    softmax_kernel<<<(unsigned)BN*NN, 256>>>(out);
}

// round 10
// speedup vs baseline: 1.8798x; 1.0284x over previous
#include <cuda_runtime.h>
#include <cstddef>

#define BN 4
#define NN 1024
#define CC 64
#define ROWS (BN*NN)   // 4096
#define IB 8           // i-rows per logits block (one warp per i-row)
#define JC 128         // j per logits block

typedef unsigned long long ull;

// device scratch (no allocation allowed)
__device__ float g_A [ROWS*CC];          // e^{2*z1}, clamped, [b*N+i][c]
__device__ float g_uT[BN*CC*NN];         // e^{2*z2}, clamped, transposed [b][c][j]

__device__ __forceinline__ float rcp_fast(float x){
    float y; asm("rcp.approx.f32 %0, %1;" : "=f"(y) : "f"(x)); return y;
}
__device__ __forceinline__ float ex2_fast(float x){
    float y; asm("ex2.approx.f32 %0, %1;" : "=f"(y) : "f"(x)); return y;
}
__device__ __forceinline__ ull fma2(ull a, ull b, ull c){
    ull d; asm("fma.rn.f32x2 %0, %1, %2, %3;" : "=l"(d) : "l"(a), "l"(b), "l"(c)); return d;
}
__device__ __forceinline__ ull mul2(ull a, ull b){
    ull d; asm("mul.rn.f32x2 %0, %1, %2;" : "=l"(d) : "l"(a), "l"(b)); return d;
}
__device__ __forceinline__ ull rcp2(ull a){
    float lo, hi;
    asm("mov.b64 {%0, %1}, %2;" : "=f"(lo), "=f"(hi) : "l"(a));
    lo = rcp_fast(lo); hi = rcp_fast(hi);
    ull d; asm("mov.b64 %0, {%1, %2};" : "=l"(d) : "f"(lo), "f"(hi)); return d;
}
__device__ __forceinline__ ull pk2(float f){
    unsigned u = __float_as_uint(f);
    return (ull)u | ((ull)u << 32);
}
#define ONE2 0x3F8000003F800000ULL
#define LOG2E 1.4426950408889634f
#define TWO_LOG2E 2.8853900817779268f
#define EXP_CAP 3.0e4f

// ---------------------------------------------------------------------------
// Kernel 1: A = clamp(e^{2*(x@W1^T)}) -> g_A (row-major)
//           u = clamp(e^{2*(x@W2^T)}) -> g_uT (TRANSPOSED, via smem tile)
// 16 rows per block; fused transpose kills the separate transpose kernel.
// ---------------------------------------------------------------------------
__global__ __launch_bounds__(256) void proj_kernel(const float* __restrict__ x,
                                                   const float* __restrict__ W1,
                                                   const float* __restrict__ W2){
    __shared__ float Ws[2][64][65];
    __shared__ float xs[16][64];
    __shared__ float us[16][65];      // u tile for transpose
    int t = threadIdx.x;

    const float4* w1v = (const float4*)W1;
    const float4* w2v = (const float4*)W2;
    #pragma unroll
    for (int p = 0; p < 4; p++){
        int idx = p*256 + t;
        int d = idx >> 4, c4 = (idx & 15) * 4;
        float4 v = w1v[idx];
        Ws[0][d][c4+0]=v.x; Ws[0][d][c4+1]=v.y; Ws[0][d][c4+2]=v.z; Ws[0][d][c4+3]=v.w;
        v = w2v[idx];
        Ws[1][d][c4+0]=v.x; Ws[1][d][c4+1]=v.y; Ws[1][d][c4+2]=v.z; Ws[1][d][c4+3]=v.w;
    }
    int row0 = blockIdx.x * 16;
    {
        int rl = t >> 4, c4 = (t & 15) * 4;
        float4 v = ((const float4*)(x + (size_t)(row0+rl)*CC))[t & 15];
        xs[rl][c4+0]=v.x; xs[rl][c4+1]=v.y; xs[rl][c4+2]=v.z; xs[rl][c4+3]=v.w;
    }
    __syncthreads();

    int m  = t >> 7;          // 0 -> A (gmem), 1 -> u (smem tile)
    int rr = (t >> 6) & 1;
    int d  = t & 63;
    #pragma unroll 4
    for (int it = 0; it < 8; it++){
        int rl = it*2 + rr;
        float acc = 0.f;
        #pragma unroll
        for (int c = 0; c < 64; c++)
            acc = fmaf(xs[rl][c], Ws[m][d][c], acc);
        float e = fminf(ex2_fast(acc * TWO_LOG2E), EXP_CAP);
        if (m == 0) g_A[(size_t)(row0+rl)*CC + d] = e;
        else        us[rl][d] = e;
    }
    __syncthreads();

    // write u transposed: g_uT[b][c][row0b + 0..15]
    int b = row0 >> 10;               // 1024 rows per batch, 16 | 1024
    int row0b = row0 & (NN-1);
    int c = t >> 2, q = t & 3;        // c in [0,64), q selects 4 j's
    float4 v = make_float4(us[4*q+0][c], us[4*q+1][c], us[4*q+2][c], us[4*q+3][c]);
    *(float4*)(g_uT + (size_t)b*CC*NN + (size_t)c*NN + row0b + 4*q) = v;
}

// ---------------------------------------------------------------------------
// Kernel 2: logits[b,i,j] = S + sum_c w'_c / D_c,
//   D_c = 1 + A[i,c]*u[j,c],  w' = -2*w3,  S = sum w3.
//   (tanh(a+b) = 1 - 2/(1+e^{2a}e^{2b}); constant numerators -> 1 FMA/term
//    at leaves, 4-channel common-denominator tree -> 1 RCP / 4 channels.)
// ---------------------------------------------------------------------------
__global__ __launch_bounds__(256) void logits_kernel(const float* __restrict__ w3f,
                                                     float* __restrict__ out){
    __shared__ float      ut[CC][JC];     // 32KB
    __shared__ ulonglong2 aw[IB][CC];     // (A,A | w',w') 8KB
    __shared__ float      w3lin[CC];

    int t = threadIdx.x;
    int lane = t & 31, il = t >> 5;       // warp = i-row
    int blk = blockIdx.x;
    int b  = blk >> 10;
    int ih = (blk >> 3) & 127;
    int jt = blk & 7;
    int i0 = ih * IB;
    int j0 = jt * JC;

    const float* uTbase = g_uT + (size_t)b*CC*NN + j0;
    #pragma unroll
    for (int k = 0; k < 8; k++){
        int idx = k*256 + t;
        int c = idx >> 5, j4 = idx & 31;
        float4 v = *(const float4*)(uTbase + (size_t)c*NN + 4*j4);
        *(float4*)&ut[c][4*j4] = v;
    }
    if (t < 128){
        int ii = t >> 4, c4 = (t & 15) * 4;
        float4 a4 = ((const float4*)(g_A + ((size_t)b*NN + i0 + ii)*CC))[t & 15];
        float4 w4 = ((const float4*)w3f)[t & 15];
        aw[ii][c4+0] = make_ulonglong2(pk2(a4.x), pk2(-2.0f*w4.x));
        aw[ii][c4+1] = make_ulonglong2(pk2(a4.y), pk2(-2.0f*w4.y));
        aw[ii][c4+2] = make_ulonglong2(pk2(a4.z), pk2(-2.0f*w4.z));
        aw[ii][c4+3] = make_ulonglong2(pk2(a4.w), pk2(-2.0f*w4.w));
    } else if (t < 192){
        w3lin[t-128] = w3f[t-128];
    }
    __syncthreads();

    float S = 0.f;
    #pragma unroll
    for (int c = 0; c < CC; c++) S += w3lin[c];

    int jb = 4*lane;
    ull acc0 = pk2(S);
    ull acc1 = pk2(S);

    #pragma unroll
    for (int g = 0; g < 16; g++){
        int c = g*4;
        ulonglong2 aw0 = aw[il][c+0];
        ulonglong2 aw1 = aw[il][c+1];
        ulonglong2 aw2 = aw[il][c+2];
        ulonglong2 aw3 = aw[il][c+3];
        ulonglong2 U0 = *(const ulonglong2*)&ut[c+0][jb];
        ulonglong2 U1 = *(const ulonglong2*)&ut[c+1][jb];
        ulonglong2 U2 = *(const ulonglong2*)&ut[c+2][jb];
        ulonglong2 U3 = *(const ulonglong2*)&ut[c+3][jb];
        {
            ull D0 = fma2(aw0.x, U0.x, ONE2);
            ull D1 = fma2(aw1.x, U1.x, ONE2);
            ull D2 = fma2(aw2.x, U2.x, ONE2);
            ull D3 = fma2(aw3.x, U3.x, ONE2);
            ull n01 = fma2(aw0.y, D1, mul2(aw1.y, D0));
            ull d01 = mul2(D0, D1);
            ull n23 = fma2(aw2.y, D3, mul2(aw3.y, D2));
            ull d23 = mul2(D2, D3);
            ull nf  = fma2(n01, d23, mul2(n23, d01));
            ull df  = mul2(d01, d23);
            acc0 = fma2(nf, rcp2(df), acc0);
        }
        {
            ull D0 = fma2(aw0.x, U0.y, ONE2);
            ull D1 = fma2(aw1.x, U1.y, ONE2);
            ull D2 = fma2(aw2.x, U2.y, ONE2);
            ull D3 = fma2(aw3.x, U3.y, ONE2);
            ull n01 = fma2(aw0.y, D1, mul2(aw1.y, D0));
            ull d01 = mul2(D0, D1);
            ull n23 = fma2(aw2.y, D3, mul2(aw3.y, D2));
            ull d23 = mul2(D2, D3);
            ull nf  = fma2(n01, d23, mul2(n23, d01));
            ull df  = mul2(d01, d23);
            acc1 = fma2(nf, rcp2(df), acc1);
        }
    }
    float* orow = out + ((size_t)(b*NN + i0 + il))*NN + j0;
    *(ulonglong2*)(orow + jb) = make_ulonglong2(acc0, acc1);
}

// ---------------------------------------------------------------------------
// Kernel 3: in-place row softmax, WARP per row (no barriers, MLP=8).
// grid 512, block 256 = 8 warps = 8 rows.
// ---------------------------------------------------------------------------
__global__ __launch_bounds__(256) void softmax_kernel(float* __restrict__ out){
    int t = threadIdx.x, lane = t & 31, w = t >> 5;
    size_t row = (size_t)blockIdx.x * 8 + w;
    float4* p = (float4*)out + row*(NN/4);

    float4 v[8];
    #pragma unroll
    for (int k = 0; k < 8; k++) v[k] = p[k*32 + lane];

    float m = -3.4e38f;
    #pragma unroll
    for (int k = 0; k < 8; k++)
        m = fmaxf(m, fmaxf(fmaxf(v[k].x, v[k].y), fmaxf(v[k].z, v[k].w)));
    #pragma unroll
    for (int o = 16; o; o >>= 1) m = fmaxf(m, __shfl_xor_sync(0xffffffffu, m, o));

    float s = 0.f;
    #pragma unroll
    for (int k = 0; k < 8; k++){
        v[k].x = ex2_fast((v[k].x - m)*LOG2E);
        v[k].y = ex2_fast((v[k].y - m)*LOG2E);
        v[k].z = ex2_fast((v[k].z - m)*LOG2E);
        v[k].w = ex2_fast((v[k].w - m)*LOG2E);
        s += (v[k].x + v[k].y) + (v[k].z + v[k].w);
    }
    #pragma unroll
    for (int o = 16; o; o >>= 1) s += __shfl_xor_sync(0xffffffffu, s, o);

    float inv = 1.0f / s;
    #pragma unroll
    for (int k = 0; k < 8; k++){
        v[k].x *= inv; v[k].y *= inv; v[k].z *= inv; v[k].w *= inv;
        p[k*32 + lane] = v[k];
    }
}

// ---------------------------------------------------------------------------
extern "C" void kernel_launch(void* const* d_in, const int* in_sizes, int n_in,
                              void* d_out, int out_size){
    const float* x  = (const float*)d_in[0];
    const float* W1 = (const float*)d_in[1];
    const float* W2 = (const float*)d_in[2];
    const float* w3 = (const float*)d_in[3];
    float* out = (float*)d_out;

    proj_kernel<<<ROWS/16, 256>>>(x, W1, W2);
    logits_kernel<<<BN*128*8, 256>>>(w3, out);
    softmax_kernel<<<ROWS/8, 256>>>(out);
}